// round 1
// baseline (speedup 1.0000x reference)
#include <cuda_runtime.h>
#include <math.h>

// Problem constants (from reference setup_inputs):
//   x:      [B=256, H=64, W=64, D=256]  -> B x K floats, K = 64*64*256 = 1048576
//   memory: [E=8,  HW=4096, D=256]      -> E x K floats
#define BN   256
#define EN   8
#define KN   1048576
#define K4N  (KN / 4)
#define CK   1024            // chunk size in floats (pass-1 tile along K)
#define CK4  (CK / 4)
#define NCH  (KN / CK)       // 1024 chunks
#define BT   32              // b-samples per block tile in pass 1
#define NBT  (BN / BT)       // 8

// Scratch (device globals -- no allocation allowed).
// g_dotp layout: [b][j][c] with j in 0..7 = dot(x_b, m_j) partial, j==8 = ||x_b||^2 partial
__device__ float g_dotp[(size_t)BN * 9 * NCH];   // 9.4 MB
__device__ float g_mpart[EN * NCH];              // ||m_e||^2 partials per chunk
__device__ int   g_experts[BN];
__device__ int   g_order[BN];
__device__ int   g_offs[EN + 1];
__device__ float g_ka[EN];
__device__ float g_kb[EN];

__device__ __forceinline__ float warp_sum(float v) {
    #pragma unroll
    for (int o = 16; o; o >>= 1)
        v += __shfl_xor_sync(0xffffffffu, v, o);
    return v;
}

// ---------------------------------------------------------------------------
// Pass 1: per-(b, chunk) partial dots + norms. m-chunk staged in smem, reused
// across 32 b's per block (m L2 traffic = 8 x 32MB; m DRAM = 32MB once).
// ---------------------------------------------------------------------------
__global__ void __launch_bounds__(256) k_dots(const float* __restrict__ x,
                                              const float* __restrict__ mem)
{
    __shared__ float4 sm[EN * CK4];   // 8 * 256 float4 = 32 KB

    const int c   = blockIdx.x;       // chunk index
    const int bt  = blockIdx.y;       // b tile index
    const int tid = threadIdx.x;
    const int w   = tid >> 5;
    const int l   = tid & 31;

    // Stage m chunk: 2048 float4 slots / 256 threads = 8 each
    const float4* m4 = (const float4*)mem;
    #pragma unroll
    for (int i = 0; i < 8; ++i) {
        int slot = tid + 256 * i;
        int e  = slot >> 8;           // /256
        int q  = slot & 255;
        sm[slot] = m4[(size_t)e * K4N + (size_t)c * CK4 + q];
    }
    __syncthreads();

    // One tile of blocks also produces ||m_e||^2 chunk partials (warp w == expert w)
    if (bt == 0) {
        float s = 0.f;
        #pragma unroll
        for (int g = 0; g < 8; ++g) {
            float4 f = sm[w * CK4 + g * 32 + l];
            s += f.x * f.x + f.y * f.y + f.z * f.z + f.w * f.w;
        }
        s = warp_sum(s);
        if (l == 0) g_mpart[w * NCH + c] = s;
    }

    const float4* x4 = (const float4*)x;

    // Each warp handles 4 b's
    #pragma unroll 1
    for (int i = 0; i < BT / 8; ++i) {
        const int b = bt * BT + i * 8 + w;
        float d[EN];
        #pragma unroll
        for (int e = 0; e < EN; ++e) d[e] = 0.f;
        float nx = 0.f;

        const float4* xp = x4 + (size_t)b * K4N + (size_t)c * CK4;
        #pragma unroll
        for (int g = 0; g < 8; ++g) {
            float4 xv = xp[g * 32 + l];
            nx += xv.x * xv.x + xv.y * xv.y + xv.z * xv.z + xv.w * xv.w;
            #pragma unroll
            for (int e = 0; e < EN; ++e) {
                float4 mv = sm[e * CK4 + g * 32 + l];
                d[e] += xv.x * mv.x + xv.y * mv.y + xv.z * mv.z + xv.w * mv.w;
            }
        }

        float* dst = g_dotp + (size_t)b * 9 * NCH;
        #pragma unroll
        for (int e = 0; e < EN; ++e) {
            float v = warp_sum(d[e]);
            if (l == 0) dst[e * NCH + c] = v;
        }
        nx = warp_sum(nx);
        if (l == 0) dst[8 * NCH + c] = nx;
    }
}

// ---------------------------------------------------------------------------
// Pass 2: reduce chunk partials per b, cosine sim, argmax (first-max rule).
// Deterministic fixed-order reductions.
// ---------------------------------------------------------------------------
__global__ void __launch_bounds__(256) k_argmax(float* __restrict__ outExp)
{
    const int b   = blockIdx.x;
    const int tid = threadIdx.x;
    const int w   = tid >> 5;
    const int l   = tid & 31;

    __shared__ float sdot[EN];
    __shared__ float smn[EN];
    __shared__ float snx;

    // dot[e = w]
    {
        const float* p = g_dotp + (size_t)b * 9 * NCH + (size_t)w * NCH;
        float v = 0.f;
        #pragma unroll
        for (int g = 0; g < NCH / 32; ++g) v += p[g * 32 + l];
        v = warp_sum(v);
        if (l == 0) sdot[w] = v;
    }
    // ||x_b||^2 (warp 0, second pass)
    if (w == 0) {
        const float* p = g_dotp + (size_t)b * 9 * NCH + (size_t)8 * NCH;
        float v = 0.f;
        #pragma unroll
        for (int g = 0; g < NCH / 32; ++g) v += p[g * 32 + l];
        v = warp_sum(v);
        if (l == 0) snx = v;
    }
    // ||m_e||^2 (redundant per block, trivial traffic)
    {
        const float* p = g_mpart + (size_t)w * NCH;
        float v = 0.f;
        #pragma unroll
        for (int g = 0; g < NCH / 32; ++g) v += p[g * 32 + l];
        v = warp_sum(v);
        if (l == 0) smn[w] = v;
    }
    __syncthreads();

    if (tid == 0) {
        float nx = sqrtf(snx);
        float best = -3.4e38f;
        int   bi   = 0;
        #pragma unroll
        for (int e = 0; e < EN; ++e) {
            float denom = fmaxf(nx * sqrtf(smn[e]), 1e-8f);
            float s = sdot[e] / denom;
            if (s > best) { best = s; bi = e; }   // strict > == first-max (jnp.argmax)
        }
        g_experts[b] = bi;
        if (outExp) outExp[b] = (float)bi;
    }
}

// ---------------------------------------------------------------------------
// Counting sort of b by expert (stable -> deterministic), plus update coeffs:
// out = ka*m + kb*sum_x, ka = count>0 ? 0.5 : 1, kb = count>0 ? 0.5/count : 0.
// ---------------------------------------------------------------------------
__global__ void k_sort()
{
    __shared__ int s_exp[BN];
    const int tid = threadIdx.x;
    s_exp[tid] = g_experts[tid];
    __syncthreads();

    if (tid == 0) {
        int counts[EN];
        #pragma unroll
        for (int e = 0; e < EN; ++e) counts[e] = 0;
        for (int b = 0; b < BN; ++b) counts[s_exp[b]]++;

        int pos[EN];
        int off = 0;
        #pragma unroll
        for (int e = 0; e < EN; ++e) {
            g_offs[e] = off;
            pos[e] = off;
            off += counts[e];
        }
        g_offs[EN] = off;

        for (int b = 0; b < BN; ++b) {
            int e = s_exp[b];
            g_order[pos[e]++] = b;
        }
        #pragma unroll
        for (int e = 0; e < EN; ++e) {
            if (counts[e] > 0) { g_ka[e] = 0.5f; g_kb[e] = 0.5f / (float)counts[e]; }
            else               { g_ka[e] = 1.0f; g_kb[e] = 0.0f; }
        }
    }
}

// ---------------------------------------------------------------------------
// Pass 3: scatter-mean update. Each thread owns one float4 column j; loops the
// sorted b-list per expert (single register accumulator, x read exactly once).
// ---------------------------------------------------------------------------
__global__ void __launch_bounds__(256) k_update(const float* __restrict__ x,
                                                const float* __restrict__ mem,
                                                float* __restrict__ outMem)
{
    __shared__ int   s_order[BN];
    __shared__ int   s_offs[EN + 1];
    __shared__ float s_ka[EN];
    __shared__ float s_kb[EN];

    const int tid = threadIdx.x;
    s_order[tid] = g_order[tid];
    if (tid < EN + 1) s_offs[tid] = g_offs[tid];
    if (tid < EN)     { s_ka[tid] = g_ka[tid]; s_kb[tid] = g_kb[tid]; }
    __syncthreads();

    const size_t j4 = (size_t)blockIdx.x * 256 + tid;
    const float4* x4 = (const float4*)x;
    const float4* m4 = (const float4*)mem;
    float4*       o4 = (float4*)outMem;

    #pragma unroll 1
    for (int e = 0; e < EN; ++e) {
        float ax = 0.f, ay = 0.f, az = 0.f, aw = 0.f;
        const int lo = s_offs[e];
        const int hi = s_offs[e + 1];
        #pragma unroll 4
        for (int i = lo; i < hi; ++i) {
            int b = s_order[i];
            float4 f = x4[(size_t)b * K4N + j4];
            ax += f.x; ay += f.y; az += f.z; aw += f.w;
        }
        const float ka = s_ka[e];
        const float kb = s_kb[e];
        float4 mv = m4[(size_t)e * K4N + j4];
        float4 ov;
        ov.x = ka * mv.x + kb * ax;
        ov.y = ka * mv.y + kb * ay;
        ov.z = ka * mv.z + kb * az;
        ov.w = ka * mv.w + kb * aw;
        o4[(size_t)e * K4N + j4] = ov;
    }
}

// ---------------------------------------------------------------------------
extern "C" void kernel_launch(void* const* d_in, const int* in_sizes, int n_in,
                              void* d_out, int out_size)
{
    const float* x   = (const float*)d_in[0];
    const float* mem = (const float*)d_in[1];
    float* out = (float*)d_out;

    const long memElems = (long)EN * KN;          // 8388608
    float* outExp = nullptr;
    float* outMem = nullptr;
    if ((long)out_size == memElems + BN) {        // concat: experts then new_memory
        outExp = out;
        outMem = out + BN;
    } else if ((long)out_size == memElems) {      // new_memory only
        outMem = out;
    } else {                                      // experts only (fallback)
        outExp = out;
    }

    dim3 g1(NCH, NBT);
    k_dots<<<g1, 256>>>(x, mem);
    k_argmax<<<BN, 256>>>(outExp);
    k_sort<<<1, 256>>>();
    if (outMem) k_update<<<K4N / 256, 256>>>(x, mem, outMem);
}

// round 2
// speedup vs baseline: 2.5545x; 2.5545x over previous
#include <cuda_runtime.h>
#include <math.h>

// Problem constants (from reference setup_inputs):
//   x:      [B=256, H=64, W=64, D=256]  -> B x K floats, K = 64*64*256 = 1048576
//   memory: [E=8,  HW=4096, D=256]      -> E x K floats
#define BN   256
#define EN   8
#define KN   1048576
#define K4N  (KN / 4)
#define CK   1024            // chunk size in floats (pass-1 tile along K)
#define CK4  (CK / 4)
#define NCH  (KN / CK)       // 1024 chunks
#define BT   32              // b-samples per block tile in pass 1
#define NBT  (BN / BT)       // 8

// Scratch (device globals -- no allocation allowed).
// g_dotp layout: [b][j][c] with j in 0..7 = dot(x_b, m_j) partial, j==8 = ||x_b||^2 partial
__device__ float g_dotp[(size_t)BN * 9 * NCH];   // 9.4 MB
__device__ float g_mpart[EN * NCH];              // ||m_e||^2 partials per chunk
__device__ int   g_experts[BN];
__device__ int   g_order[BN];
__device__ int   g_offs[EN + 1];
__device__ float g_ka[EN];
__device__ float g_kb[EN];

__device__ __forceinline__ float warp_sum(float v) {
    #pragma unroll
    for (int o = 16; o; o >>= 1)
        v += __shfl_xor_sync(0xffffffffu, v, o);
    return v;
}

// ---------------------------------------------------------------------------
// Pass 1: per-(b, chunk) partial dots + norms.
// Register-blocked over 4 b's per warp: each smem expert vector is loaded ONCE
// and FMA'd into 4 accumulators (4x less smem traffic than b-at-a-time).
// FFMA is the binding pipe (~2.1G scalar FMAs chip-wide).
// ---------------------------------------------------------------------------
__global__ void __launch_bounds__(256) k_dots(const float* __restrict__ x,
                                              const float* __restrict__ mem)
{
    __shared__ float4 sm[EN * CK4];   // 8 * 256 float4 = 32 KB

    const int c   = blockIdx.x;       // chunk index
    const int bt  = blockIdx.y;       // b tile index
    const int tid = threadIdx.x;
    const int w   = tid >> 5;
    const int l   = tid & 31;

    // Stage m chunk: 2048 float4 slots / 256 threads = 8 each
    const float4* m4 = (const float4*)mem;
    #pragma unroll
    for (int i = 0; i < 8; ++i) {
        int slot = tid + 256 * i;
        int e  = slot >> 8;           // /256
        int q  = slot & 255;
        sm[slot] = m4[(size_t)e * K4N + (size_t)c * CK4 + q];
    }
    __syncthreads();

    // One tile of blocks also produces ||m_e||^2 chunk partials (warp w == expert w)
    if (bt == 0) {
        float s = 0.f;
        #pragma unroll
        for (int g = 0; g < 8; ++g) {
            float4 f = sm[w * CK4 + g * 32 + l];
            s += f.x * f.x + f.y * f.y + f.z * f.z + f.w * f.w;
        }
        s = warp_sum(s);
        if (l == 0) g_mpart[w * NCH + c] = s;
    }

    const float4* x4 = (const float4*)x;

    // Warp w handles b's: bt*32 + {0,1,2,3}*8 + w, all four concurrently.
    float d[4][EN];
    float nx[4];
    #pragma unroll
    for (int i = 0; i < 4; ++i) {
        nx[i] = 0.f;
        #pragma unroll
        for (int e = 0; e < EN; ++e) d[i][e] = 0.f;
    }

    const float4* xp0 = x4 + (size_t)(bt * BT + 0 * 8 + w) * K4N + (size_t)c * CK4;
    const float4* xp1 = x4 + (size_t)(bt * BT + 1 * 8 + w) * K4N + (size_t)c * CK4;
    const float4* xp2 = x4 + (size_t)(bt * BT + 2 * 8 + w) * K4N + (size_t)c * CK4;
    const float4* xp3 = x4 + (size_t)(bt * BT + 3 * 8 + w) * K4N + (size_t)c * CK4;

    #pragma unroll
    for (int g = 0; g < 8; ++g) {
        const int o = g * 32 + l;
        float4 xv[4];
        xv[0] = xp0[o];
        xv[1] = xp1[o];
        xv[2] = xp2[o];
        xv[3] = xp3[o];

        #pragma unroll
        for (int i = 0; i < 4; ++i)
            nx[i] += xv[i].x * xv[i].x + xv[i].y * xv[i].y
                   + xv[i].z * xv[i].z + xv[i].w * xv[i].w;

        #pragma unroll
        for (int e = 0; e < EN; ++e) {
            const float4 mv = sm[e * CK4 + o];   // ONE smem load, used 4x
            #pragma unroll
            for (int i = 0; i < 4; ++i)
                d[i][e] += xv[i].x * mv.x + xv[i].y * mv.y
                         + xv[i].z * mv.z + xv[i].w * mv.w;
        }
    }

    #pragma unroll
    for (int i = 0; i < 4; ++i) {
        const int b = bt * BT + i * 8 + w;
        float* dst = g_dotp + (size_t)b * 9 * NCH;
        #pragma unroll
        for (int e = 0; e < EN; ++e) {
            float v = warp_sum(d[i][e]);
            if (l == 0) dst[e * NCH + c] = v;
        }
        float v = warp_sum(nx[i]);
        if (l == 0) dst[8 * NCH + c] = v;
    }
}

// ---------------------------------------------------------------------------
// Pass 2: reduce chunk partials per b, cosine sim, argmax (first-max rule).
// Deterministic fixed-order reductions.
// ---------------------------------------------------------------------------
__global__ void __launch_bounds__(256) k_argmax(float* __restrict__ outExp)
{
    const int b   = blockIdx.x;
    const int tid = threadIdx.x;
    const int w   = tid >> 5;
    const int l   = tid & 31;

    __shared__ float sdot[EN];
    __shared__ float smn[EN];
    __shared__ float snx;

    // dot[e = w]
    {
        const float* p = g_dotp + (size_t)b * 9 * NCH + (size_t)w * NCH;
        float v = 0.f;
        #pragma unroll
        for (int g = 0; g < NCH / 32; ++g) v += p[g * 32 + l];
        v = warp_sum(v);
        if (l == 0) sdot[w] = v;
    }
    // ||x_b||^2 (warp 0, second pass)
    if (w == 0) {
        const float* p = g_dotp + (size_t)b * 9 * NCH + (size_t)8 * NCH;
        float v = 0.f;
        #pragma unroll
        for (int g = 0; g < NCH / 32; ++g) v += p[g * 32 + l];
        v = warp_sum(v);
        if (l == 0) snx = v;
    }
    // ||m_e||^2 (redundant per block, trivial traffic)
    {
        const float* p = g_mpart + (size_t)w * NCH;
        float v = 0.f;
        #pragma unroll
        for (int g = 0; g < NCH / 32; ++g) v += p[g * 32 + l];
        v = warp_sum(v);
        if (l == 0) smn[w] = v;
    }
    __syncthreads();

    if (tid == 0) {
        float nx = sqrtf(snx);
        float best = -3.4e38f;
        int   bi   = 0;
        #pragma unroll
        for (int e = 0; e < EN; ++e) {
            float denom = fmaxf(nx * sqrtf(smn[e]), 1e-8f);
            float s = sdot[e] / denom;
            if (s > best) { best = s; bi = e; }   // strict > == first-max (jnp.argmax)
        }
        g_experts[b] = bi;
        if (outExp) outExp[b] = (float)bi;
    }
}

// ---------------------------------------------------------------------------
// Counting sort of b by expert (stable -> deterministic), plus update coeffs:
// out = ka*m + kb*sum_x, ka = count>0 ? 0.5 : 1, kb = count>0 ? 0.5/count : 0.
// ---------------------------------------------------------------------------
__global__ void k_sort()
{
    __shared__ int s_exp[BN];
    const int tid = threadIdx.x;
    s_exp[tid] = g_experts[tid];
    __syncthreads();

    if (tid == 0) {
        int counts[EN];
        #pragma unroll
        for (int e = 0; e < EN; ++e) counts[e] = 0;
        for (int b = 0; b < BN; ++b) counts[s_exp[b]]++;

        int pos[EN];
        int off = 0;
        #pragma unroll
        for (int e = 0; e < EN; ++e) {
            g_offs[e] = off;
            pos[e] = off;
            off += counts[e];
        }
        g_offs[EN] = off;

        for (int b = 0; b < BN; ++b) {
            int e = s_exp[b];
            g_order[pos[e]++] = b;
        }
        #pragma unroll
        for (int e = 0; e < EN; ++e) {
            if (counts[e] > 0) { g_ka[e] = 0.5f; g_kb[e] = 0.5f / (float)counts[e]; }
            else               { g_ka[e] = 1.0f; g_kb[e] = 0.0f; }
        }
    }
}

// ---------------------------------------------------------------------------
// Pass 3: scatter-mean update. Each thread owns one float4 column j; loops the
// sorted b-list per expert (single register accumulator, x read exactly once).
// 85.6% DRAM already -- near roofline.
// ---------------------------------------------------------------------------
__global__ void __launch_bounds__(256) k_update(const float* __restrict__ x,
                                                const float* __restrict__ mem,
                                                float* __restrict__ outMem)
{
    __shared__ int   s_order[BN];
    __shared__ int   s_offs[EN + 1];
    __shared__ float s_ka[EN];
    __shared__ float s_kb[EN];

    const int tid = threadIdx.x;
    s_order[tid] = g_order[tid];
    if (tid < EN + 1) s_offs[tid] = g_offs[tid];
    if (tid < EN)     { s_ka[tid] = g_ka[tid]; s_kb[tid] = g_kb[tid]; }
    __syncthreads();

    const size_t j4 = (size_t)blockIdx.x * 256 + tid;
    const float4* x4 = (const float4*)x;
    const float4* m4 = (const float4*)mem;
    float4*       o4 = (float4*)outMem;

    #pragma unroll 1
    for (int e = 0; e < EN; ++e) {
        float ax = 0.f, ay = 0.f, az = 0.f, aw = 0.f;
        const int lo = s_offs[e];
        const int hi = s_offs[e + 1];
        #pragma unroll 4
        for (int i = lo; i < hi; ++i) {
            int b = s_order[i];
            float4 f = x4[(size_t)b * K4N + j4];
            ax += f.x; ay += f.y; az += f.z; aw += f.w;
        }
        const float ka = s_ka[e];
        const float kb = s_kb[e];
        float4 mv = m4[(size_t)e * K4N + j4];
        float4 ov;
        ov.x = ka * mv.x + kb * ax;
        ov.y = ka * mv.y + kb * ay;
        ov.z = ka * mv.z + kb * az;
        ov.w = ka * mv.w + kb * aw;
        o4[(size_t)e * K4N + j4] = ov;
    }
}

// ---------------------------------------------------------------------------
extern "C" void kernel_launch(void* const* d_in, const int* in_sizes, int n_in,
                              void* d_out, int out_size)
{
    const float* x   = (const float*)d_in[0];
    const float* mem = (const float*)d_in[1];
    float* out = (float*)d_out;

    const long memElems = (long)EN * KN;          // 8388608
    float* outExp = nullptr;
    float* outMem = nullptr;
    if ((long)out_size == memElems + BN) {        // concat: experts then new_memory
        outExp = out;
        outMem = out + BN;
    } else if ((long)out_size == memElems) {      // new_memory only
        outMem = out;
    } else {                                      // experts only (fallback)
        outExp = out;
    }

    dim3 g1(NCH, NBT);
    k_dots<<<g1, 256>>>(x, mem);
    k_argmax<<<BN, 256>>>(outExp);
    k_sort<<<1, 256>>>();
    if (outMem) k_update<<<K4N / 256, 256>>>(x, mem, outMem);
}